// round 1
// baseline (speedup 1.0000x reference)
#include <cuda_runtime.h>
#include <math.h>

#define BB 256
#define IND 512
#define OUTD 512
#define ED 256
#define DELTA_C 0.1f
#define LN_EPS_C 1e-5f

typedef unsigned long long u64;

// Scratch (device globals — no allocation allowed)
__device__ float g_Wt[IND * OUTD];      // Wt[i][o] = W[o][i]
__device__ float g_scores[IND * OUTD];  // scores[i][o]
__device__ float g_M[IND * OUTD];       // M[i][o] = |W[o,i]| * sigmoid(LN(scores)[i][o])

// ---- packed f32x2 helpers (sm_100+ only; ptxas won't auto-fuse) ----
__device__ __forceinline__ u64 pack2(float lo, float hi) {
    u64 r; asm("mov.b64 %0, {%1,%2};" : "=l"(r) : "f"(lo), "f"(hi)); return r;
}
#define FMA2(d,a,b,c) asm("fma.rn.f32x2 %0,%1,%2,%3;" : "=l"(d) : "l"(a),"l"(b),"l"(c))
#define MUL2(d,a,b)   asm("mul.rn.f32x2 %0,%1,%2;"    : "=l"(d) : "l"(a),"l"(b))
#define ADD2(d,a,b)   asm("add.rn.f32x2 %0,%1,%2;"    : "=l"(d) : "l"(a),"l"(b))
#define UNPACK2(lo,hi,v) asm("mov.b64 {%0,%1}, %2;" : "=f"(lo),"=f"(hi) : "l"(v))

// ============================================================
// Kernel 1: transpose W[o][i] -> Wt[i][o]
// grid (16,16), block (32,8)
// ============================================================
__global__ void kernel_transpose(const float* __restrict__ W) {
    __shared__ float tile[32][33];
    int tx = threadIdx.x, ty = threadIdx.y;
    int c = blockIdx.x * 32 + tx;
    int r0 = blockIdx.y * 32;
#pragma unroll
    for (int j = 0; j < 32; j += 8)
        tile[ty + j][tx] = W[(r0 + ty + j) * IND + c];
    __syncthreads();
    int c2 = blockIdx.y * 32 + tx;
    int r2 = blockIdx.x * 32;
#pragma unroll
    for (int j = 0; j < 32; j += 8)
        g_Wt[(r2 + ty + j) * OUTD + c2] = tile[tx][ty + j];
}

// ============================================================
// Kernel 2: scores[i][o] = attn_b[o] + sum_e pred_emb[i][e]*attn_w[o][e]
// grid (4 o-tiles, 32 i-tiles), block 128 (one o per thread), 16 i per block
// Packed f32x2 over i-pairs (pred_emb tile stored [e][ii] in shared).
// ============================================================
__global__ __launch_bounds__(128) void kernel_scores(
    const float* __restrict__ PE, const float* __restrict__ AW,
    const float* __restrict__ AB) {
    __shared__ float pe[32][18];  // [e][ii], stride 18 keeps 8B alignment
    const int tid = threadIdx.x;
    const int o = blockIdx.x * 128 + tid;
    const int i0 = blockIdx.y * 16;

    u64 acc[8];
    const u64 z = pack2(0.f, 0.f);
#pragma unroll
    for (int j = 0; j < 8; j++) acc[j] = z;

    const float* awrow = AW + o * ED;

    for (int e0 = 0; e0 < ED; e0 += 32) {
        __syncthreads();
        // load 16x32 pred_emb tile, transposed into pe[e][ii]
#pragma unroll
        for (int idx = tid; idx < 512; idx += 128) {
            int ii = idx >> 5, e = idx & 31;
            pe[e][ii] = PE[(i0 + ii) * ED + e0 + e];
        }
        __syncthreads();
#pragma unroll
        for (int e4 = 0; e4 < 32; e4 += 4) {
            float4 w4 = *(const float4*)(awrow + e0 + e4);
            float we[4] = {w4.x, w4.y, w4.z, w4.w};
#pragma unroll
            for (int k = 0; k < 4; k++) {
                u64 ww = pack2(we[k], we[k]);
#pragma unroll
                for (int j = 0; j < 8; j++) {
                    u64 p = *(const u64*)&pe[e4 + k][2 * j];
                    FMA2(acc[j], p, ww, acc[j]);
                }
            }
        }
    }
    float bo = AB[o];
#pragma unroll
    for (int j = 0; j < 8; j++) {
        float lo, hi; UNPACK2(lo, hi, acc[j]);
        g_scores[(i0 + 2 * j) * OUTD + o] = lo + bo;
        g_scores[(i0 + 2 * j + 1) * OUTD + o] = hi + bo;
    }
}

// ============================================================
// Kernel 3: LayerNorm(row) -> sigmoid -> M[i][o] = |Wt[i][o]| * sig
// grid 128 (4 rows each), block 128 (4 warps, warp w reduces row w)
// ============================================================
__global__ __launch_bounds__(128) void kernel_ln(
    const float* __restrict__ LG, const float* __restrict__ LB) {
    const int tid = threadIdx.x;
    const int i0 = blockIdx.x * 4;
    const int w = tid >> 5, lane = tid & 31;
    __shared__ float mus[4], rss[4];

    {
        const float* row = g_scores + (i0 + w) * OUTD;
        float s = 0.f, s2 = 0.f;
#pragma unroll
        for (int k = 0; k < 16; k++) {
            float v = row[lane + 32 * k];
            s += v; s2 += v * v;
        }
#pragma unroll
        for (int off = 16; off > 0; off >>= 1) {
            s  += __shfl_xor_sync(0xffffffffu, s,  off);
            s2 += __shfl_xor_sync(0xffffffffu, s2, off);
        }
        if (lane == 0) {
            float mu = s * (1.f / OUTD);
            float var = s2 * (1.f / OUTD) - mu * mu;
            mus[w] = mu;
            rss[w] = rsqrtf(var + LN_EPS_C);
        }
    }
    __syncthreads();
#pragma unroll
    for (int ii = 0; ii < 4; ii++) {
        float mu = mus[ii], rs = rss[ii];
        const int i = i0 + ii;
#pragma unroll
        for (int j = 0; j < 4; j++) {
            int oo = tid + j * 128;
            float s = g_scores[i * OUTD + oo];
            float v = (s - mu) * rs * LG[oo] + LB[oo];
            float sig = 1.f / (1.f + __expf(-v));
            g_M[i * OUTD + oo] = fabsf(g_Wt[i * OUTD + oo]) * sig;
        }
    }
}

// ============================================================
// Kernel 4 (main): out[b,o] = x@Wt + 0.1*(max_i t*M - sum_i t*M)
// grid (4 o-tiles, 64 b-tiles), block 64 threads.
// Thread owns 2 consecutive o (packed f32x2), 4 batches in registers.
// x/t pre-duplicated in shared as ((x,x),(t,t)) -> single LDS.128 per (b,i).
// ============================================================
__global__ __launch_bounds__(64) void kernel_main(
    const float* __restrict__ X, float* __restrict__ out) {
    __shared__ ulonglong2 xt[4][IND];  // .x=(x,x) .y=(t,t)  (32 KB)
    const int tid = threadIdx.x;
    const int o = blockIdx.x * 128 + tid * 2;
    const int b0 = blockIdx.y * 4;

    for (int idx = tid; idx < 4 * IND; idx += 64) {
        int b = idx >> 9, i = idx & 511;
        float xv = X[(b0 + b) * IND + i];
        float tv = xv * fabsf(xv);
        xt[b][i] = make_ulonglong2(pack2(xv, xv), pack2(tv, tv));
    }
    __syncthreads();

    u64 acc1[4], acc2[4];
    float mxlo[4], mxhi[4];
    const u64 z = pack2(0.f, 0.f);
#pragma unroll
    for (int b = 0; b < 4; b++) {
        acc1[b] = z; acc2[b] = z;
        mxlo[b] = -INFINITY; mxhi[b] = -INFINITY;
    }

    const float* wp = g_Wt + o;
    const float* mp = g_M + o;
#pragma unroll 4
    for (int i = 0; i < IND; i++) {
        u64 w2 = *(const u64*)(wp + i * OUTD);
        u64 m2 = *(const u64*)(mp + i * OUTD);
#pragma unroll
        for (int b = 0; b < 4; b++) {
            ulonglong2 v = xt[b][i];
            FMA2(acc1[b], v.x, w2, acc1[b]);
            u64 p2; MUL2(p2, v.y, m2);
            ADD2(acc2[b], acc2[b], p2);
            float plo, phi; UNPACK2(plo, phi, p2);
            mxlo[b] = fmaxf(mxlo[b], plo);
            mxhi[b] = fmaxf(mxhi[b], phi);
        }
    }

#pragma unroll
    for (int b = 0; b < 4; b++) {
        float a1lo, a1hi, a2lo, a2hi;
        UNPACK2(a1lo, a1hi, acc1[b]);
        UNPACK2(a2lo, a2hi, acc2[b]);
        float2 r;
        r.x = a1lo + DELTA_C * (mxlo[b] - a2lo);
        r.y = a1hi + DELTA_C * (mxhi[b] - a2hi);
        *(float2*)(out + (b0 + b) * OUTD + o) = r;
    }
}

// ============================================================
extern "C" void kernel_launch(void* const* d_in, const int* in_sizes, int n_in,
                              void* d_out, int out_size) {
    const float* x  = (const float*)d_in[0];
    const float* w  = (const float*)d_in[1];
    const float* pe = (const float*)d_in[2];
    const float* aw = (const float*)d_in[3];
    const float* ab = (const float*)d_in[4];
    const float* lg = (const float*)d_in[5];
    const float* lb = (const float*)d_in[6];
    float* out = (float*)d_out;

    kernel_transpose<<<dim3(16, 16), dim3(32, 8)>>>(w);
    kernel_scores<<<dim3(4, 32), 128>>>(pe, aw, ab);
    kernel_ln<<<128, 128>>>(lg, lb);
    kernel_main<<<dim3(4, 64), 64>>>(x, out);
}

// round 2
// speedup vs baseline: 1.4096x; 1.4096x over previous
#include <cuda_runtime.h>
#include <math.h>

#define BB 256
#define IND 512
#define OUTD 512
#define ED 256
#define DELTA_C 0.1f
#define LN_EPS_C 1e-5f

typedef unsigned long long u64;

// Scratch (device globals — no allocation allowed)
__device__ float g_Wt[IND * OUTD];      // Wt[i][o] = W[o][i]
__device__ float g_scores[IND * OUTD];  // scores[i][o]
__device__ float g_M[IND * OUTD];       // M[i][o] = |W[o,i]| * sigmoid(LN(scores)[i][o])

// ---- packed f32x2 helpers (sm_100+ only; ptxas won't auto-fuse) ----
__device__ __forceinline__ u64 pack2(float lo, float hi) {
    u64 r; asm("mov.b64 %0, {%1,%2};" : "=l"(r) : "f"(lo), "f"(hi)); return r;
}
#define FMA2(d,a,b,c) asm("fma.rn.f32x2 %0,%1,%2,%3;" : "=l"(d) : "l"(a),"l"(b),"l"(c))
#define MUL2(d,a,b)   asm("mul.rn.f32x2 %0,%1,%2;"    : "=l"(d) : "l"(a),"l"(b))
#define ADD2(d,a,b)   asm("add.rn.f32x2 %0,%1,%2;"    : "=l"(d) : "l"(a),"l"(b))
#define UNPACK2(lo,hi,v) asm("mov.b64 {%0,%1}, %2;" : "=f"(lo),"=f"(hi) : "l"(v))

// ============================================================
// Kernel 1: transpose W[o][i] -> Wt[i][o]
// ============================================================
__global__ void kernel_transpose(const float* __restrict__ W) {
    __shared__ float tile[32][33];
    int tx = threadIdx.x, ty = threadIdx.y;
    int c = blockIdx.x * 32 + tx;
    int r0 = blockIdx.y * 32;
#pragma unroll
    for (int j = 0; j < 32; j += 8)
        tile[ty + j][tx] = W[(r0 + ty + j) * IND + c];
    __syncthreads();
    int c2 = blockIdx.y * 32 + tx;
    int r2 = blockIdx.x * 32;
#pragma unroll
    for (int j = 0; j < 32; j += 8)
        g_Wt[(r2 + ty + j) * OUTD + c2] = tile[tx][ty + j];
}

// ============================================================
// Kernel 2: scores[i][o] = attn_b[o] + sum_e pred_emb[i][e]*attn_w[o][e]
// ============================================================
__global__ __launch_bounds__(128) void kernel_scores(
    const float* __restrict__ PE, const float* __restrict__ AW,
    const float* __restrict__ AB) {
    __shared__ float pe[32][18];
    const int tid = threadIdx.x;
    const int o = blockIdx.x * 128 + tid;
    const int i0 = blockIdx.y * 16;

    u64 acc[8];
    const u64 z = pack2(0.f, 0.f);
#pragma unroll
    for (int j = 0; j < 8; j++) acc[j] = z;

    const float* awrow = AW + o * ED;

    for (int e0 = 0; e0 < ED; e0 += 32) {
        __syncthreads();
#pragma unroll
        for (int idx = tid; idx < 512; idx += 128) {
            int ii = idx >> 5, e = idx & 31;
            pe[e][ii] = PE[(i0 + ii) * ED + e0 + e];
        }
        __syncthreads();
#pragma unroll
        for (int e4 = 0; e4 < 32; e4 += 4) {
            float4 w4 = *(const float4*)(awrow + e0 + e4);
            float we[4] = {w4.x, w4.y, w4.z, w4.w};
#pragma unroll
            for (int k = 0; k < 4; k++) {
                u64 ww = pack2(we[k], we[k]);
#pragma unroll
                for (int j = 0; j < 8; j++) {
                    u64 p = *(const u64*)&pe[e4 + k][2 * j];
                    FMA2(acc[j], p, ww, acc[j]);
                }
            }
        }
    }
    float bo = AB[o];
#pragma unroll
    for (int j = 0; j < 8; j++) {
        float lo, hi; UNPACK2(lo, hi, acc[j]);
        g_scores[(i0 + 2 * j) * OUTD + o] = lo + bo;
        g_scores[(i0 + 2 * j + 1) * OUTD + o] = hi + bo;
    }
}

// ============================================================
// Kernel 3: LayerNorm(row) -> sigmoid -> M[i][o]
// ============================================================
__global__ __launch_bounds__(128) void kernel_ln(
    const float* __restrict__ LG, const float* __restrict__ LB) {
    const int tid = threadIdx.x;
    const int i0 = blockIdx.x * 4;
    const int w = tid >> 5, lane = tid & 31;
    __shared__ float mus[4], rss[4];

    {
        const float* row = g_scores + (i0 + w) * OUTD;
        float s = 0.f, s2 = 0.f;
#pragma unroll
        for (int k = 0; k < 16; k++) {
            float v = row[lane + 32 * k];
            s += v; s2 += v * v;
        }
#pragma unroll
        for (int off = 16; off > 0; off >>= 1) {
            s  += __shfl_xor_sync(0xffffffffu, s,  off);
            s2 += __shfl_xor_sync(0xffffffffu, s2, off);
        }
        if (lane == 0) {
            float mu = s * (1.f / OUTD);
            float var = s2 * (1.f / OUTD) - mu * mu;
            mus[w] = mu;
            rss[w] = rsqrtf(var + LN_EPS_C);
        }
    }
    __syncthreads();
#pragma unroll
    for (int ii = 0; ii < 4; ii++) {
        float mu = mus[ii], rs = rss[ii];
        const int i = i0 + ii;
#pragma unroll
        for (int j = 0; j < 4; j++) {
            int oo = tid + j * 128;
            float s = g_scores[i * OUTD + oo];
            float v = (s - mu) * rs * LG[oo] + LB[oo];
            float sig = 1.f / (1.f + __expf(-v));
            g_M[i * OUTD + oo] = fabsf(g_Wt[i * OUTD + oo]) * sig;
        }
    }
}

// ============================================================
// Kernel 4 (main): out[b,o] = x@Wt + 0.1*(max_i t*M - sum_i t*M)
//
// grid (8 o-tiles of 64, 32 b-tiles of 8), block 256 = 8 warps.
// Thread (to = tid&31, si = tid>>5): o-pair to, i-chunk si (64 i's).
// Each warp = one i-chunk -> 2048 warps total, ~14/SM.
// xt[b][i] = ((x,x),(t,t)) packed, broadcast LDS.128 in the hot loop.
// Partial results (acc1 - 0.1*acc2 precombined + running max) are reduced
// across si-groups through shared memory (stride-33 planes, conflict-free),
// reusing the xt smem region.
// ============================================================
#define MAIN_SMEM (8 * IND * 16)  // 64 KB

__global__ __launch_bounds__(256) void kernel_main(
    const float* __restrict__ X, float* __restrict__ out) {
    extern __shared__ char smem_raw[];
    ulonglong2 (*xt)[IND] = (ulonglong2 (*)[IND])smem_raw;  // [8][512], 64KB
    float* red = (float*)smem_raw;  // reused after compute phase

    const int tid = threadIdx.x;
    const int to = tid & 31;   // o-pair index within tile
    const int si = tid >> 5;   // i-chunk (= warp id)
    const int o = blockIdx.x * 64 + to * 2;
    const int b0 = blockIdx.y * 8;

    // Stage x (and t = x*|x|) for 8 batches, duplicated for f32x2.
    for (int idx = tid; idx < 8 * IND; idx += 256) {
        int b = idx >> 9, i = idx & 511;
        float xv = X[(b0 + b) * IND + i];
        float tv = xv * fabsf(xv);
        xt[b][i] = make_ulonglong2(pack2(xv, xv), pack2(tv, tv));
    }
    __syncthreads();

    u64 acc1[8], acc2[8];
    float mxlo[8], mxhi[8];
    const u64 z = pack2(0.f, 0.f);
#pragma unroll
    for (int b = 0; b < 8; b++) {
        acc1[b] = z; acc2[b] = z;
        mxlo[b] = -INFINITY; mxhi[b] = -INFINITY;
    }

    const float* wp = g_Wt + o;
    const float* mp = g_M + o;
    const int i_end = si * 64 + 64;
#pragma unroll 2
    for (int i = si * 64; i < i_end; i++) {
        u64 w2 = *(const u64*)(wp + i * OUTD);
        u64 m2 = *(const u64*)(mp + i * OUTD);
#pragma unroll
        for (int b = 0; b < 8; b++) {
            ulonglong2 v = xt[b][i];
            FMA2(acc1[b], v.x, w2, acc1[b]);
            u64 p2; MUL2(p2, v.y, m2);
            ADD2(acc2[b], acc2[b], p2);
            float plo, phi; UNPACK2(plo, phi, p2);
            mxlo[b] = fmaxf(mxlo[b], plo);
            mxhi[b] = fmaxf(mxhi[b], phi);
        }
    }

    __syncthreads();  // xt no longer needed; reuse as reduction buffer

    // red planes: [k][b][si][to], k in {sum_lo, sum_hi, max_lo, max_hi}
    // idx = ((k*8 + b)*8 + si)*33 + to  -> 4*8*8*33*4B = 33.8KB
#define RIDX(k, b, s, t) ((((k) * 8 + (b)) * 8 + (s)) * 33 + (t))
#pragma unroll
    for (int b = 0; b < 8; b++) {
        float a1lo, a1hi, a2lo, a2hi;
        UNPACK2(a1lo, a1hi, acc1[b]);
        UNPACK2(a2lo, a2hi, acc2[b]);
        red[RIDX(0, b, si, to)] = a1lo - DELTA_C * a2lo;
        red[RIDX(1, b, si, to)] = a1hi - DELTA_C * a2hi;
        red[RIDX(2, b, si, to)] = mxlo[b];
        red[RIDX(3, b, si, to)] = mxhi[b];
    }
    __syncthreads();

    // Final combine: thread (b2 = tid>>5, to2 = tid&31) reduces 8 si-groups.
    const int b2 = tid >> 5;
    const int to2 = tid & 31;
    float slo = 0.f, shi = 0.f, Mlo = -INFINITY, Mhi = -INFINITY;
#pragma unroll
    for (int s = 0; s < 8; s++) {
        slo += red[RIDX(0, b2, s, to2)];
        shi += red[RIDX(1, b2, s, to2)];
        Mlo = fmaxf(Mlo, red[RIDX(2, b2, s, to2)]);
        Mhi = fmaxf(Mhi, red[RIDX(3, b2, s, to2)]);
    }
    float2 r;
    r.x = slo + DELTA_C * Mlo;
    r.y = shi + DELTA_C * Mhi;
    *(float2*)(out + (b0 + b2) * OUTD + blockIdx.x * 64 + to2 * 2) = r;
#undef RIDX
}

// ============================================================
extern "C" void kernel_launch(void* const* d_in, const int* in_sizes, int n_in,
                              void* d_out, int out_size) {
    const float* x  = (const float*)d_in[0];
    const float* w  = (const float*)d_in[1];
    const float* pe = (const float*)d_in[2];
    const float* aw = (const float*)d_in[3];
    const float* ab = (const float*)d_in[4];
    const float* lg = (const float*)d_in[5];
    const float* lb = (const float*)d_in[6];
    float* out = (float*)d_out;

    static int smem_set = 0;
    if (!smem_set) {
        cudaFuncSetAttribute(kernel_main,
                             cudaFuncAttributeMaxDynamicSharedMemorySize,
                             MAIN_SMEM);
        smem_set = 1;
    }

    kernel_transpose<<<dim3(16, 16), dim3(32, 8)>>>(w);
    kernel_scores<<<dim3(4, 32), 128>>>(pe, aw, ab);
    kernel_ln<<<128, 128>>>(lg, lb);
    kernel_main<<<dim3(8, 32), 256, MAIN_SMEM>>>(x, out);
}

// round 3
// speedup vs baseline: 1.4509x; 1.0293x over previous
#include <cuda_runtime.h>
#include <math.h>

#define BB 256
#define IND 512
#define OUTD 512
#define ED 256
#define DELTA_C 0.1f
#define LN_EPS_C 1e-5f

typedef unsigned long long u64;

// Scratch (device globals — no allocation allowed)
__device__ float g_Wt[IND * OUTD];      // Wt[i][o] = W[o][i]
__device__ float g_scores[IND * OUTD];  // scores[i][o]
__device__ float4 g_WM[IND * (OUTD / 2)];  // (w_lo, w_hi, m_lo, m_hi) per (i, o-pair)

// ---- packed f32x2 helpers ----
__device__ __forceinline__ u64 pack2(float lo, float hi) {
    u64 r; asm("mov.b64 %0, {%1,%2};" : "=l"(r) : "f"(lo), "f"(hi)); return r;
}
#define FMA2(d,a,b,c) asm("fma.rn.f32x2 %0,%1,%2,%3;" : "=l"(d) : "l"(a),"l"(b),"l"(c))
#define MUL2(d,a,b)   asm("mul.rn.f32x2 %0,%1,%2;"    : "=l"(d) : "l"(a),"l"(b))
#define UNPACK2(lo,hi,v) asm("mov.b64 {%0,%1}, %2;" : "=f"(lo),"=f"(hi) : "l"(v))

// ============================================================
// Kernel 1: transpose W[o][i] -> Wt[i][o]
// ============================================================
__global__ void kernel_transpose(const float* __restrict__ W) {
    __shared__ float tile[32][33];
    int tx = threadIdx.x, ty = threadIdx.y;
    int c = blockIdx.x * 32 + tx;
    int r0 = blockIdx.y * 32;
#pragma unroll
    for (int j = 0; j < 32; j += 8)
        tile[ty + j][tx] = W[(r0 + ty + j) * IND + c];
    __syncthreads();
    int c2 = blockIdx.y * 32 + tx;
    int r2 = blockIdx.x * 32;
#pragma unroll
    for (int j = 0; j < 32; j += 8)
        g_Wt[(r2 + ty + j) * OUTD + c2] = tile[tx][ty + j];
}

// ============================================================
// Kernel 2: scores[i][o] = attn_b[o] + sum_e pred_emb[i][e]*attn_w[o][e]
// ============================================================
__global__ __launch_bounds__(128) void kernel_scores(
    const float* __restrict__ PE, const float* __restrict__ AW,
    const float* __restrict__ AB) {
    __shared__ float pe[32][18];
    const int tid = threadIdx.x;
    const int o = blockIdx.x * 128 + tid;
    const int i0 = blockIdx.y * 16;

    u64 acc[8];
    const u64 z = pack2(0.f, 0.f);
#pragma unroll
    for (int j = 0; j < 8; j++) acc[j] = z;

    const float* awrow = AW + o * ED;

    for (int e0 = 0; e0 < ED; e0 += 32) {
        __syncthreads();
#pragma unroll
        for (int idx = tid; idx < 512; idx += 128) {
            int ii = idx >> 5, e = idx & 31;
            pe[e][ii] = PE[(i0 + ii) * ED + e0 + e];
        }
        __syncthreads();
#pragma unroll
        for (int e4 = 0; e4 < 32; e4 += 4) {
            float4 w4 = *(const float4*)(awrow + e0 + e4);
            float we[4] = {w4.x, w4.y, w4.z, w4.w};
#pragma unroll
            for (int k = 0; k < 4; k++) {
                u64 ww = pack2(we[k], we[k]);
#pragma unroll
                for (int j = 0; j < 8; j++) {
                    u64 p = *(const u64*)&pe[e4 + k][2 * j];
                    FMA2(acc[j], p, ww, acc[j]);
                }
            }
        }
    }
    float bo = AB[o];
#pragma unroll
    for (int j = 0; j < 8; j++) {
        float lo, hi; UNPACK2(lo, hi, acc[j]);
        g_scores[(i0 + 2 * j) * OUTD + o] = lo + bo;
        g_scores[(i0 + 2 * j + 1) * OUTD + o] = hi + bo;
    }
}

// ============================================================
// Kernel 3: LayerNorm -> sigmoid -> write interleaved g_WM float4
// grid 128 (4 rows each), block 128 (4 warps for stats)
// ============================================================
__global__ __launch_bounds__(128) void kernel_ln(
    const float* __restrict__ LG, const float* __restrict__ LB) {
    const int tid = threadIdx.x;
    const int i0 = blockIdx.x * 4;
    const int w = tid >> 5, lane = tid & 31;
    __shared__ float mus[4], rss[4];

    {
        const float* row = g_scores + (i0 + w) * OUTD;
        float s = 0.f, s2 = 0.f;
#pragma unroll
        for (int k = 0; k < 16; k++) {
            float v = row[lane + 32 * k];
            s += v; s2 += v * v;
        }
#pragma unroll
        for (int off = 16; off > 0; off >>= 1) {
            s  += __shfl_xor_sync(0xffffffffu, s,  off);
            s2 += __shfl_xor_sync(0xffffffffu, s2, off);
        }
        if (lane == 0) {
            float mu = s * (1.f / OUTD);
            float var = s2 * (1.f / OUTD) - mu * mu;
            mus[w] = mu;
            rss[w] = rsqrtf(var + LN_EPS_C);
        }
    }
    __syncthreads();
#pragma unroll
    for (int ii = 0; ii < 4; ii++) {
        float mu = mus[ii], rs = rss[ii];
        const int i = i0 + ii;
#pragma unroll
        for (int j = 0; j < 2; j++) {
            int p = tid + j * 128;  // o-pair index [0,256)
            float2 s2v = *(const float2*)(g_scores + i * OUTD + 2 * p);
            float2 w2v = *(const float2*)(g_Wt + i * OUTD + 2 * p);
            float glo = LG[2 * p],     blo = LB[2 * p];
            float ghi = LG[2 * p + 1], bhi = LB[2 * p + 1];
            float vlo = (s2v.x - mu) * rs * glo + blo;
            float vhi = (s2v.y - mu) * rs * ghi + bhi;
            float siglo = 1.f / (1.f + __expf(-vlo));
            float sighi = 1.f / (1.f + __expf(-vhi));
            float4 q;
            q.x = w2v.x; q.y = w2v.y;
            q.z = fabsf(w2v.x) * siglo;
            q.w = fabsf(w2v.y) * sighi;
            g_WM[i * (OUTD / 2) + p] = q;
        }
    }
}

// ============================================================
// Kernel 4 (main): out[b,o] = x@Wt + 0.1*(max_i t*M - sum_i t*M)
//
// grid (16 o-tiles of 32, 32 b-tiles of 8), block 256, 3 blocks/SM.
// Thread: to = tid&15 (o-pair in tile), si = tid>>4 (i-chunk of 32).
// Accumulates c = sum(x*w) - 0.1*sum(t*M) directly (one less acc array);
// running max kept separately. One prefetched LDG.128 per i per thread
// (w_lo,w_hi,m_lo,m_hi interleaved). Cross-si reduction through smem.
// ============================================================
#define MAIN_SMEM (8 * IND * 16)  // 64 KB

__global__ __launch_bounds__(256, 3) void kernel_main(
    const float* __restrict__ X, float* __restrict__ out) {
    extern __shared__ char smem_raw[];
    ulonglong2 (*xt)[IND] = (ulonglong2 (*)[IND])smem_raw;  // [8][512], 64KB
    float* red = (float*)smem_raw;  // reused after compute phase

    const int tid = threadIdx.x;
    const int to = tid & 15;
    const int si = tid >> 4;       // [0,16)
    const int b0 = blockIdx.y * 8;

    // Stage x and t = x*|x|, duplicated for f32x2 broadcast loads.
    for (int idx = tid; idx < 8 * IND; idx += 256) {
        int b = idx >> 9, i = idx & 511;
        float xv = X[(b0 + b) * IND + i];
        float tv = xv * fabsf(xv);
        xt[b][i] = make_ulonglong2(pack2(xv, xv), pack2(tv, tv));
    }
    __syncthreads();

    u64 c[8];
    float mxlo[8], mxhi[8];
    const u64 z = pack2(0.f, 0.f);
    const u64 n01 = pack2(-DELTA_C, -DELTA_C);
#pragma unroll
    for (int b = 0; b < 8; b++) {
        c[b] = z;
        mxlo[b] = -INFINITY; mxhi[b] = -INFINITY;
    }

    const float4* __restrict__ wmp = g_WM + blockIdx.x * 16 + to;
    const int ib = si * 32;

#pragma unroll 1
    for (int ii = 0; ii < 32; ii += 4) {
        float4 q[4];
#pragma unroll
        for (int k = 0; k < 4; k++)
            q[k] = __ldg(wmp + (u64)(ib + ii + k) * (OUTD / 2));
#pragma unroll
        for (int k = 0; k < 4; k++) {
            const int i = ib + ii + k;
            u64 w2 = pack2(q[k].x, q[k].y);
            u64 m2 = pack2(q[k].z, q[k].w);
#pragma unroll
            for (int b = 0; b < 8; b++) {
                ulonglong2 v = xt[b][i];
                FMA2(c[b], v.x, w2, c[b]);
                u64 p2; MUL2(p2, v.y, m2);
                FMA2(c[b], p2, n01, c[b]);
                float plo, phi; UNPACK2(plo, phi, p2);
                mxlo[b] = fmaxf(mxlo[b], plo);
                mxhi[b] = fmaxf(mxhi[b], phi);
            }
        }
    }

    __syncthreads();  // xt no longer needed; reuse as reduction buffer

    // red planes: [k][b][si][to], k in {c_lo, c_hi, max_lo, max_hi}
#define RIDX(k, b, s, t) ((((k) * 8 + (b)) * 16 + (s)) * 17 + (t))
#pragma unroll
    for (int b = 0; b < 8; b++) {
        float clo, chi;
        UNPACK2(clo, chi, c[b]);
        red[RIDX(0, b, si, to)] = clo;
        red[RIDX(1, b, si, to)] = chi;
        red[RIDX(2, b, si, to)] = mxlo[b];
        red[RIDX(3, b, si, to)] = mxhi[b];
    }
    __syncthreads();

    // Final combine: 128 active threads, each reduces 16 si-groups.
    if (tid < 128) {
        const int b2 = tid >> 4;
        const int to2 = tid & 15;
        float slo = 0.f, shi = 0.f, Mlo = -INFINITY, Mhi = -INFINITY;
#pragma unroll
        for (int s = 0; s < 16; s++) {
            slo += red[RIDX(0, b2, s, to2)];
            shi += red[RIDX(1, b2, s, to2)];
            Mlo = fmaxf(Mlo, red[RIDX(2, b2, s, to2)]);
            Mhi = fmaxf(Mhi, red[RIDX(3, b2, s, to2)]);
        }
        float2 r;
        r.x = slo + DELTA_C * Mlo;
        r.y = shi + DELTA_C * Mhi;
        *(float2*)(out + (b0 + b2) * OUTD + blockIdx.x * 32 + to2 * 2) = r;
    }
#undef RIDX
}

// ============================================================
extern "C" void kernel_launch(void* const* d_in, const int* in_sizes, int n_in,
                              void* d_out, int out_size) {
    const float* x  = (const float*)d_in[0];
    const float* w  = (const float*)d_in[1];
    const float* pe = (const float*)d_in[2];
    const float* aw = (const float*)d_in[3];
    const float* ab = (const float*)d_in[4];
    const float* lg = (const float*)d_in[5];
    const float* lb = (const float*)d_in[6];
    float* out = (float*)d_out;

    static int smem_set = 0;
    if (!smem_set) {
        cudaFuncSetAttribute(kernel_main,
                             cudaFuncAttributeMaxDynamicSharedMemorySize,
                             MAIN_SMEM);
        smem_set = 1;
    }

    kernel_transpose<<<dim3(16, 16), dim3(32, 8)>>>(w);
    kernel_scores<<<dim3(4, 32), 128>>>(pe, aw, ab);
    kernel_ln<<<128, 128>>>(lg, lb);
    kernel_main<<<dim3(16, 32), 256, MAIN_SMEM>>>(x, out);
}